// round 1
// baseline (speedup 1.0000x reference)
#include <cuda_runtime.h>
#include <cuda_bf16.h>
#include <cstdint>

// FPQuantizer: per-row absmax clip is the identity (maxval = row max|x|),
// so the reference reduces to a pure elementwise fp8-e4m3-style "flex" quantizer:
//   bias = bf16(2^4 - log2(448) + log2(2 - 2^-4) - 1) = 7.15625 (exact bf16)
//   L    = max(floor(log2|x| + bias), 1)
//   s    = 2^(L - 5 - bias) = 2^(L-12) * 2^(-0.15625)
//   out  = rint(x / s) * s     (round half to even)
//
// All transcendentals replaced with exponent-field bit tricks to stay HBM-bound:
//   floor(log2|x| + 7.15625) = e + 7 + (mant >= 2^0.84375)
// where |x| = 2^e * mant, mant in [1,2).

#define QT_THRESH 1.79470907f   // 2^(27/32) = 2^0.84375, fp32-rounded
#define QT_C      0.89735454f   // 2^(-0.15625), fp32-rounded
#define QT_CINV   1.11438674f   // 2^(+0.15625), fp32-rounded

__device__ __forceinline__ float fpq_quantize(float x) {
    uint32_t b = __float_as_uint(x) & 0x7fffffffu;          // |x| bits
    int e = (int)(b >> 23) - 127;                            // biased exponent -> unbiased
    float mant = __uint_as_float((b & 0x7fffffu) | 0x3f800000u); // mantissa in [1,2)
    int L = e + 7 + (mant >= QT_THRESH ? 1 : 0);             // floor(log2|x| + bias)
    L = (L < 1) ? 1 : L;                                     // max(log_scales, 1)
    // x == 0 (b==0): e=-127, mant=1.0 -> L=-120 -> clamped to 1; rint(0*r)*s = 0. Matches ref.
    int k = L - 12;                                          // L - MBITS - 7
    // scale = 2^k * 2^-0.15625 ; rscale = 2^-k * 2^+0.15625 (exact pow2 via exponent field)
    float p    = __uint_as_float((uint32_t)(k + 127) << 23);
    float pinv = __uint_as_float((uint32_t)(127 - k) << 23);
    float s = p * QT_C;
    float r = pinv * QT_CINV;
    return rintf(x * r) * s;                                 // rint = round-half-even (jnp.round)
}

__global__ __launch_bounds__(256) void FPQuantizer_76312978915927_kernel(
    const float4* __restrict__ x, float4* __restrict__ out, int n4)
{
    int i = blockIdx.x * blockDim.x + threadIdx.x;
    if (i < n4) {
        float4 v = x[i];
        float4 q;
        q.x = fpq_quantize(v.x);
        q.y = fpq_quantize(v.y);
        q.z = fpq_quantize(v.z);
        q.w = fpq_quantize(v.w);
        out[i] = q;
    }
}

// Scalar tail kernel (defensive; out_size here is divisible by 4 so it won't launch)
__global__ void FPQuantizer_tail_kernel(const float* __restrict__ x,
                                        float* __restrict__ out,
                                        int start, int n)
{
    int i = start + blockIdx.x * blockDim.x + threadIdx.x;
    if (i < n) out[i] = fpq_quantize(x[i]);
}

extern "C" void kernel_launch(void* const* d_in, const int* in_sizes, int n_in,
                              void* d_out, int out_size)
{
    const float* x = (const float*)d_in[0];
    float* out = (float*)d_out;

    int n = out_size;
    int n4 = n >> 2;

    const int threads = 256;
    if (n4 > 0) {
        int blocks = (n4 + threads - 1) / threads;
        FPQuantizer_76312978915927_kernel<<<blocks, threads>>>(
            (const float4*)x, (float4*)out, n4);
    }
    int tail_start = n4 << 2;
    int tail = n - tail_start;
    if (tail > 0) {
        FPQuantizer_tail_kernel<<<1, 128>>>(x, out, tail_start, n);
    }
}